// round 5
// baseline (speedup 1.0000x reference)
#include <cuda_runtime.h>
#include <cuda_bf16.h>
#include <cstdint>

// Problem constants (fixed by the dataset)
#define NN 50000
#define EE 800000
#define IN_C 256
#define HID_C 128
#define OUT_C 64

// ---------------------------------------------------------------------------
// Scratch (device globals). All float4-accessed buffers 16B-aligned.
// ---------------------------------------------------------------------------
__device__ int   g_deg[NN];
__device__ float g_dinv[NN];
__device__ int   g_rowptr[NN + 1];
__device__ int   g_cursor[NN];
__device__ int   g_blocksums[64];
__device__ int   g_csr[EE];
__device__ __align__(16) float g_h1[(size_t)NN * HID_C];
__device__ __align__(16) float g_t1[(size_t)NN * HID_C];
__device__ __align__(16) float g_h2[(size_t)NN * OUT_C];

// packed fp32x2 FMA: (c.lo,c.hi) += (a.lo*b.lo, a.hi*b.hi)
#define FMA2(c, a, b) \
    asm("fma.rn.f32x2 %0, %1, %2, %0;" : "+l"(c) : "l"(a), "l"(b))

// ---------------------------------------------------------------------------
// Degree / norm. edge_index is INT32 (JAX x64 disabled).
// ---------------------------------------------------------------------------
__global__ void k_clear_deg() {
    int i = blockIdx.x * blockDim.x + threadIdx.x;
    if (i < NN) g_deg[i] = 0;
}

__global__ void k_count_deg(const int* __restrict__ dst) {
    int e = blockIdx.x * blockDim.x + threadIdx.x;
    if (e < EE) {
        unsigned d = (unsigned)dst[e];
        if (d < NN) atomicAdd(&g_deg[d], 1);
    }
}

__global__ void k_dinv() {
    int i = blockIdx.x * blockDim.x + threadIdx.x;
    if (i < NN) g_dinv[i] = rsqrtf((float)(g_deg[i] + 1));  // +1 self-loop
}

// ---------------------------------------------------------------------------
// Exclusive scan of g_deg -> g_rowptr
// ---------------------------------------------------------------------------
__global__ void k_scan_block() {
    __shared__ int sm[1024];
    int i = blockIdx.x * 1024 + threadIdx.x;
    int v = (i < NN) ? g_deg[i] : 0;
    sm[threadIdx.x] = v;
    __syncthreads();
#pragma unroll
    for (int off = 1; off < 1024; off <<= 1) {
        int t = (threadIdx.x >= off) ? sm[threadIdx.x - off] : 0;
        __syncthreads();
        sm[threadIdx.x] += t;
        __syncthreads();
    }
    int incl = sm[threadIdx.x];
    if (i < NN) g_rowptr[i] = incl - v;
    if (threadIdx.x == 1023) g_blocksums[blockIdx.x] = incl;
}

__global__ void k_scan_sums(int nb) {
    if (threadIdx.x == 0 && blockIdx.x == 0) {
        int acc = 0;
        for (int b = 0; b < nb; b++) {
            int v = g_blocksums[b];
            g_blocksums[b] = acc;
            acc += v;
        }
    }
}

__global__ void k_scan_add() {
    int i = blockIdx.x * blockDim.x + threadIdx.x;
    if (i < NN) {
        int r = g_rowptr[i] + g_blocksums[i >> 10];
        g_rowptr[i] = r;
        g_cursor[i] = r;
    }
    if (i == 0) g_rowptr[NN] = EE;
}

__global__ void k_fill_csr(const int* __restrict__ src,
                           const int* __restrict__ dst) {
    int e = blockIdx.x * blockDim.x + threadIdx.x;
    if (e < EE) {
        unsigned d = (unsigned)dst[e];
        unsigned s = (unsigned)src[e];
        if (d < NN && s < NN) {
            int pos = atomicAdd(&g_cursor[d], 1);
            if ((unsigned)pos < EE) g_csr[pos] = (int)s;
        }
    }
}

// ---------------------------------------------------------------------------
// GEMM core (FFMA2): C[row,:] = (A[row,:] @ W) * g_dinv[row]
//   Accumulator paired along M: each 64-bit acc holds rows (m, m+1).
//   A-operands: direct LDS.128 of consecutive-M shared tile (natural pairs).
//   B-operands: W duplicated in shared as (w,w) pairs -> direct LDS.128.
//   Inner loop per k: 6x LDS.128 + 32x FFMA2 (64 FMAs) per thread.
// ---------------------------------------------------------------------------
template <int BM, int BN, int BK, int TM, int TN>
__device__ __forceinline__ void gemm_rowscale_core(
        const float* __restrict__ A, const float* __restrict__ W,
        float* __restrict__ C, int M, int K) {
    constexpr int THREADS = (BM / TM) * (BN / TN);
    static_assert(TM == 8 && TN == 8, "layout assumes 8x8 micro-tile");
    // As row stride = BM+4 floats (528B for BM=128) keeps 16B alignment and
    // staggers banks across k.
    __shared__ __align__(16) float As[BK][BM + 4];
    __shared__ __align__(16) float Ws2[BK][2 * BN];   // duplicated pairs

    const int tid = threadIdx.x;
    const int tx  = tid % (BN / TN);
    const int ty  = tid / (BN / TN);
    const int rowBase = blockIdx.x * BM;

    unsigned long long acc[TM / 2][TN];  // (row m, row m+1) packed fp32x2
#pragma unroll
    for (int i = 0; i < TM / 2; i++)
#pragma unroll
        for (int j = 0; j < TN; j++) acc[i][j] = 0ull;

    for (int k0 = 0; k0 < K; k0 += BK) {
        // load A tile (BM x BK), transpose into As[k][m]
        constexpr int A4 = BM * BK / 4;
#pragma unroll
        for (int i = tid; i < A4; i += THREADS) {
            int r  = i / (BK / 4);
            int kq = i % (BK / 4);
            int grow = rowBase + r;
            float4 v = make_float4(0.f, 0.f, 0.f, 0.f);
            if (grow < M)
                v = *reinterpret_cast<const float4*>(A + (size_t)grow * K + k0 + kq * 4);
            As[kq * 4 + 0][r] = v.x;
            As[kq * 4 + 1][r] = v.y;
            As[kq * 4 + 2][r] = v.z;
            As[kq * 4 + 3][r] = v.w;
        }
        // load W tile (BK x BN), duplicated: Ws2[k][2n]=Ws2[k][2n+1]=W[k][n]
        constexpr int W4 = BK * BN / 4;
#pragma unroll
        for (int i = tid; i < W4; i += THREADS) {
            int kk = i / (BN / 4);
            int nq = i % (BN / 4);
            float4 v = *reinterpret_cast<const float4*>(W + (size_t)(k0 + kk) * BN + nq * 4);
            float4 d0 = make_float4(v.x, v.x, v.y, v.y);
            float4 d1 = make_float4(v.z, v.z, v.w, v.w);
            *reinterpret_cast<float4*>(&Ws2[kk][nq * 8 + 0]) = d0;
            *reinterpret_cast<float4*>(&Ws2[kk][nq * 8 + 4]) = d1;
        }
        __syncthreads();

#pragma unroll
        for (int k = 0; k < BK; k++) {
            // a: 8 consecutive M rows -> 4 packed pairs via 2x LDS.128
            longlong2 a01 = *reinterpret_cast<const longlong2*>(&As[k][ty * TM]);
            longlong2 a23 = *reinterpret_cast<const longlong2*>(&As[k][ty * TM + 4]);
            unsigned long long ap[4] = {
                (unsigned long long)a01.x, (unsigned long long)a01.y,
                (unsigned long long)a23.x, (unsigned long long)a23.y };
            // b: 8 duplicated (w,w) pairs via 4x LDS.128
            unsigned long long bp[8];
#pragma unroll
            for (int q = 0; q < 4; q++) {
                longlong2 b = *reinterpret_cast<const longlong2*>(
                    &Ws2[k][2 * tx * TN + 4 * q]);
                bp[2 * q + 0] = (unsigned long long)b.x;
                bp[2 * q + 1] = (unsigned long long)b.y;
            }
#pragma unroll
            for (int i = 0; i < TM / 2; i++)
#pragma unroll
                for (int j = 0; j < TN; j++)
                    FMA2(acc[i][j], ap[i], bp[j]);
        }
        __syncthreads();
    }

    // epilogue: unpack pairs, scale by dinv[row], vector stores
#pragma unroll
    for (int i = 0; i < TM / 2; i++) {
        int r0 = rowBase + ty * TM + 2 * i;
        float lo[TN], hi[TN];
#pragma unroll
        for (int j = 0; j < TN; j++) {
            float2 f = *reinterpret_cast<float2*>(&acc[i][j]);
            lo[j] = f.x;  hi[j] = f.y;
        }
        if (r0 < M) {
            float s = g_dinv[r0];
            float4 v0 = make_float4(lo[0]*s, lo[1]*s, lo[2]*s, lo[3]*s);
            float4 v1 = make_float4(lo[4]*s, lo[5]*s, lo[6]*s, lo[7]*s);
            *reinterpret_cast<float4*>(C + (size_t)r0 * BN + tx * TN + 0) = v0;
            *reinterpret_cast<float4*>(C + (size_t)r0 * BN + tx * TN + 4) = v1;
        }
        if (r0 + 1 < M) {
            float s = g_dinv[r0 + 1];
            float4 v0 = make_float4(hi[0]*s, hi[1]*s, hi[2]*s, hi[3]*s);
            float4 v1 = make_float4(hi[4]*s, hi[5]*s, hi[6]*s, hi[7]*s);
            *reinterpret_cast<float4*>(C + (size_t)(r0 + 1) * BN + tx * TN + 0) = v0;
            *reinterpret_cast<float4*>(C + (size_t)(r0 + 1) * BN + tx * TN + 4) = v1;
        }
    }
}

__global__ void __launch_bounds__(256)
k_gemm1(const float* __restrict__ x, const float* __restrict__ W1) {
    gemm_rowscale_core<128, HID_C, 16, 8, 8>(x, W1, g_h1, NN, IN_C);
}

__global__ void __launch_bounds__(128)
k_gemm2(const float* __restrict__ W2) {
    gemm_rowscale_core<128, OUT_C, 16, 8, 8>(g_t1, W2, g_h2, NN, HID_C);
}

// ---------------------------------------------------------------------------
// Aggregation: out[i] = act( dinv[i] * (hs[i] + sum_{s in N(i)} hs[s]) + b )
// ---------------------------------------------------------------------------
template <int C, bool RELU>
__device__ __forceinline__ void aggregate_core(
        const float* __restrict__ hs, const float* __restrict__ bias,
        float* __restrict__ out) {
    constexpr int G   = C / 4;     // threads per node
    constexpr int NPB = 128 / G;   // nodes per block
    const int local = threadIdx.x / G;
    const int lane  = threadIdx.x % G;
    const int node  = blockIdx.x * NPB + local;
    if (node >= NN) return;

    const float4* base = reinterpret_cast<const float4*>(hs);
    float4 acc = base[(size_t)node * G + lane];    // self-loop term
    const int beg = g_rowptr[node];
    const int end = g_rowptr[node + 1];
#pragma unroll 4
    for (int e = beg; e < end; e++) {
        int s = g_csr[e];
        float4 v = base[(size_t)s * G + lane];
        acc.x += v.x; acc.y += v.y; acc.z += v.z; acc.w += v.w;
    }
    const float d = g_dinv[node];
    float4 b = reinterpret_cast<const float4*>(bias)[lane];
    acc.x = acc.x * d + b.x;
    acc.y = acc.y * d + b.y;
    acc.z = acc.z * d + b.z;
    acc.w = acc.w * d + b.w;
    if (RELU) {
        acc.x = fmaxf(acc.x, 0.f);
        acc.y = fmaxf(acc.y, 0.f);
        acc.z = fmaxf(acc.z, 0.f);
        acc.w = fmaxf(acc.w, 0.f);
    }
    reinterpret_cast<float4*>(out)[(size_t)node * G + lane] = acc;
}

__global__ void __launch_bounds__(128)
k_agg1(const float* __restrict__ b1) {
    aggregate_core<HID_C, true>(g_h1, b1, g_t1);
}

__global__ void __launch_bounds__(128)
k_agg2(const float* __restrict__ b2, float* __restrict__ out) {
    aggregate_core<OUT_C, false>(g_h2, b2, out);
}

// ---------------------------------------------------------------------------
// Launch
// ---------------------------------------------------------------------------
extern "C" void kernel_launch(void* const* d_in, const int* in_sizes, int n_in,
                              void* d_out, int out_size) {
    const float* x   = (const float*)d_in[0];
    const int*   ei  = (const int*)d_in[1];     // int32 edge_index
    const float* W1  = (const float*)d_in[2];
    const float* b1  = (const float*)d_in[3];
    const float* W2  = (const float*)d_in[4];
    const float* b2  = (const float*)d_in[5];
    float*       out = (float*)d_out;

    const int* src = ei;         // edge_index[0]
    const int* dst = ei + EE;    // edge_index[1]

    const int TB = 256;
    const int nBlkN = (NN + TB - 1) / TB;
    const int nBlkE = (EE + TB - 1) / TB;
    const int nScan = (NN + 1023) / 1024;  // 49

    // --- normalization + CSR build ---
    k_clear_deg<<<nBlkN, TB>>>();
    k_count_deg<<<nBlkE, TB>>>(dst);
    k_dinv<<<nBlkN, TB>>>();
    k_scan_block<<<nScan, 1024>>>();
    k_scan_sums<<<1, 32>>>(nScan);
    k_scan_add<<<nBlkN, TB>>>();
    k_fill_csr<<<nBlkE, TB>>>(src, dst);

    // --- layer 1 ---
    {
        constexpr int BM = 128;
        int grid = (NN + BM - 1) / BM;
        k_gemm1<<<grid, 256>>>(x, W1);
    }
    {
        constexpr int NPB = 128 / (HID_C / 4);  // 4 nodes / block
        int grid = (NN + NPB - 1) / NPB;
        k_agg1<<<grid, 128>>>(b1);
    }
    // --- layer 2 ---
    {
        constexpr int BM = 128;
        int grid = (NN + BM - 1) / BM;
        k_gemm2<<<grid, 128>>>(W2);
    }
    {
        constexpr int NPB = 128 / (OUT_C / 4);  // 8 nodes / block
        int grid = (NN + NPB - 1) / NPB;
        k_agg2<<<grid, 128>>>(b2, out);
    }
}

// round 8
// speedup vs baseline: 2.4274x; 2.4274x over previous
#include <cuda_runtime.h>
#include <cuda_bf16.h>
#include <cstdint>

// Problem constants (fixed by the dataset)
#define NN 50000
#define EE 800000
#define IN_C 256
#define HID_C 128
#define OUT_C 64

// ---------------------------------------------------------------------------
// Scratch (device globals). All float4-accessed buffers 16B-aligned.
// ---------------------------------------------------------------------------
__device__ int   g_deg[NN];
__device__ float g_dinv[NN];
__device__ int   g_rowptr[NN + 1];
__device__ int   g_cursor[NN];
__device__ int   g_blocksums[64];
__device__ int   g_csr[EE];
__device__ __align__(16) float g_h1[(size_t)NN * HID_C];
__device__ __align__(16) float g_t1[(size_t)NN * HID_C];
__device__ __align__(16) float g_h2[(size_t)NN * OUT_C];
// Weight images: W^T in bf16 hi/lo, row-major [n][k] (k contiguous)
__device__ __align__(16) __nv_bfloat16 g_Wt1h[HID_C * IN_C];
__device__ __align__(16) __nv_bfloat16 g_Wt1l[HID_C * IN_C];
__device__ __align__(16) __nv_bfloat16 g_Wt2h[OUT_C * HID_C];
__device__ __align__(16) __nv_bfloat16 g_Wt2l[OUT_C * HID_C];

// ---------------------------------------------------------------------------
// PTX helpers (arch-agnostic: ldmatrix sm_75+, mma bf16 sm_80+)
// ---------------------------------------------------------------------------
__device__ __forceinline__ uint32_t smem_u32(const void* p) {
    uint32_t a;
    asm("{ .reg .u64 t; cvta.to.shared.u64 t, %1; cvt.u32.u64 %0, t; }"
        : "=r"(a) : "l"(p));
    return a;
}
__device__ __forceinline__ void ldsm_x4(uint32_t* r, uint32_t addr) {
    asm volatile("ldmatrix.sync.aligned.m8n8.x4.shared.b16 {%0,%1,%2,%3}, [%4];"
                 : "=r"(r[0]), "=r"(r[1]), "=r"(r[2]), "=r"(r[3]) : "r"(addr));
}
__device__ __forceinline__ void mma_bf16(float* d, const uint32_t* a,
                                         const uint32_t* b) {
    asm volatile(
        "mma.sync.aligned.m16n8k16.row.col.f32.bf16.bf16.f32 "
        "{%0,%1,%2,%3}, {%4,%5,%6,%7}, {%8,%9}, {%0,%1,%2,%3};"
        : "+f"(d[0]), "+f"(d[1]), "+f"(d[2]), "+f"(d[3])
        : "r"(a[0]), "r"(a[1]), "r"(a[2]), "r"(a[3]), "r"(b[0]), "r"(b[1]));
}
__device__ __forceinline__ uint32_t pack2(__nv_bfloat16 lo, __nv_bfloat16 hi) {
    return ((uint32_t)__bfloat16_as_ushort(hi) << 16) | __bfloat16_as_ushort(lo);
}

// ---------------------------------------------------------------------------
// Degree / norm. edge_index is INT32 (JAX x64 disabled).
// ---------------------------------------------------------------------------
__global__ void k_clear_deg() {
    int i = blockIdx.x * blockDim.x + threadIdx.x;
    if (i < NN) g_deg[i] = 0;
}
__global__ void k_count_deg(const int* __restrict__ dst) {
    int e = blockIdx.x * blockDim.x + threadIdx.x;
    if (e < EE) {
        unsigned d = (unsigned)dst[e];
        if (d < NN) atomicAdd(&g_deg[d], 1);
    }
}
__global__ void k_dinv() {
    int i = blockIdx.x * blockDim.x + threadIdx.x;
    if (i < NN) g_dinv[i] = rsqrtf((float)(g_deg[i] + 1));
}
__global__ void k_scan_block() {
    __shared__ int sm[1024];
    int i = blockIdx.x * 1024 + threadIdx.x;
    int v = (i < NN) ? g_deg[i] : 0;
    sm[threadIdx.x] = v;
    __syncthreads();
#pragma unroll
    for (int off = 1; off < 1024; off <<= 1) {
        int t = (threadIdx.x >= off) ? sm[threadIdx.x - off] : 0;
        __syncthreads();
        sm[threadIdx.x] += t;
        __syncthreads();
    }
    int incl = sm[threadIdx.x];
    if (i < NN) g_rowptr[i] = incl - v;
    if (threadIdx.x == 1023) g_blocksums[blockIdx.x] = incl;
}
__global__ void k_scan_sums(int nb) {
    if (threadIdx.x == 0 && blockIdx.x == 0) {
        int acc = 0;
        for (int b = 0; b < nb; b++) {
            int v = g_blocksums[b];
            g_blocksums[b] = acc;
            acc += v;
        }
    }
}
__global__ void k_scan_add() {
    int i = blockIdx.x * blockDim.x + threadIdx.x;
    if (i < NN) {
        int r = g_rowptr[i] + g_blocksums[i >> 10];
        g_rowptr[i] = r;
        g_cursor[i] = r;
    }
    if (i == 0) g_rowptr[NN] = EE;
}
__global__ void k_fill_csr(const int* __restrict__ src,
                           const int* __restrict__ dst) {
    int e = blockIdx.x * blockDim.x + threadIdx.x;
    if (e < EE) {
        unsigned d = (unsigned)dst[e];
        unsigned s = (unsigned)src[e];
        if (d < NN && s < NN) {
            int pos = atomicAdd(&g_cursor[d], 1);
            if ((unsigned)pos < EE) g_csr[pos] = (int)s;
        }
    }
}

// ---------------------------------------------------------------------------
// Weight split: W[K,N] fp32 -> Wt_hi/Wt_lo bf16, layout [n][k] (k contiguous)
// ---------------------------------------------------------------------------
template <int K, int N>
__device__ __forceinline__ void conv_core(const float* __restrict__ W,
                                          __nv_bfloat16* th, __nv_bfloat16* tl) {
    int i = blockIdx.x * blockDim.x + threadIdx.x;
    if (i >= K * N) return;
    int k = i / N, n = i % N;
    float v = W[i];
    __nv_bfloat16 h = __float2bfloat16(v);
    __nv_bfloat16 l = __float2bfloat16(v - __bfloat162float(h));
    th[(size_t)n * K + k] = h;
    tl[(size_t)n * K + k] = l;
}
__global__ void k_conv1(const float* __restrict__ W) {
    conv_core<IN_C, HID_C>(W, g_Wt1h, g_Wt1l);
}
__global__ void k_conv2(const float* __restrict__ W) {
    conv_core<HID_C, OUT_C>(W, g_Wt2h, g_Wt2l);
}

// ---------------------------------------------------------------------------
// bf16x3 HMMA GEMM: C[row,:] = (A[row,:] @ W) * g_dinv[row]
//   CTA: 128 rows x N, 8 warps (16 rows each). K-chunks of 32 staged in smem.
//   3 products per k-step: Ahi*Whi + Ahi*Wlo + Alo*Whi (fp32 accumulate).
// ---------------------------------------------------------------------------
template <int K, int N>
__device__ __forceinline__ void mma_gemm_core(
        const float* __restrict__ A,
        const __nv_bfloat16* __restrict__ Wth,
        const __nv_bfloat16* __restrict__ Wtl,
        float* __restrict__ C) {
    constexpr int KC  = 32;   // k per chunk
    constexpr int KCP = 40;   // row stride in bf16 (80B: 16B-mult, conflict-free)
    __shared__ __align__(16) __nv_bfloat16 sAh[128 * KCP];
    __shared__ __align__(16) __nv_bfloat16 sAl[128 * KCP];
    __shared__ __align__(16) __nv_bfloat16 sWh[N * KCP];
    __shared__ __align__(16) __nv_bfloat16 sWl[N * KCP];

    const int tid  = threadIdx.x;
    const int lane = tid & 31;
    const int warp = tid >> 5;
    const int wrow = warp * 16;
    const int rowBase = blockIdx.x * 128;

    const uint32_t sAh_b = smem_u32(sAh), sAl_b = smem_u32(sAl);
    const uint32_t sWh_b = smem_u32(sWh), sWl_b = smem_u32(sWl);

    float acc[N / 8][4];
#pragma unroll
    for (int t = 0; t < N / 8; t++)
#pragma unroll
        for (int q = 0; q < 4; q++) acc[t][q] = 0.f;

    const int g  = lane >> 3;       // ldmatrix lane-group
    const int r8 = lane & 7;

    for (int c = 0; c < K / KC; c++) {
        if (c) __syncthreads();
        // --- stage A chunk: fp32 -> bf16 hi/lo ---
#pragma unroll
        for (int i = tid; i < 128 * KC / 4; i += 256) {
            int r = i >> 3, kq = i & 7;
            int grow = rowBase + r;
            float4 v = make_float4(0.f, 0.f, 0.f, 0.f);
            if (grow < NN)
                v = *reinterpret_cast<const float4*>(
                        A + (size_t)grow * K + c * KC + kq * 4);
            __nv_bfloat16 hx = __float2bfloat16(v.x), hy = __float2bfloat16(v.y);
            __nv_bfloat16 hz = __float2bfloat16(v.z), hw = __float2bfloat16(v.w);
            __nv_bfloat16 lx = __float2bfloat16(v.x - __bfloat162float(hx));
            __nv_bfloat16 ly = __float2bfloat16(v.y - __bfloat162float(hy));
            __nv_bfloat16 lz = __float2bfloat16(v.z - __bfloat162float(hz));
            __nv_bfloat16 lw = __float2bfloat16(v.w - __bfloat162float(hw));
            *reinterpret_cast<uint2*>(&sAh[r * KCP + kq * 4]) =
                make_uint2(pack2(hx, hy), pack2(hz, hw));
            *reinterpret_cast<uint2*>(&sAl[r * KCP + kq * 4]) =
                make_uint2(pack2(lx, ly), pack2(lz, lw));
        }
        // --- stage W chunk (already bf16 images, [n][k]) ---
#pragma unroll
        for (int i = tid; i < N * 4; i += 256) {
            int n = i >> 2, q = i & 3;
            const float4* sh = reinterpret_cast<const float4*>(
                Wth + (size_t)n * K + c * KC + q * 8);
            const float4* sl = reinterpret_cast<const float4*>(
                Wtl + (size_t)n * K + c * KC + q * 8);
            *reinterpret_cast<float4*>(&sWh[n * KCP + q * 8]) = *sh;
            *reinterpret_cast<float4*>(&sWl[n * KCP + q * 8]) = *sl;
        }
        __syncthreads();

#pragma unroll
        for (int ks = 0; ks < KC / 16; ks++) {
            int k0 = ks * 16;
            // A fragments (hi, lo): rows wrow..wrow+16, k0..k0+16
            uint32_t ah[4], al[4];
            {
                int arow = wrow + r8 + ((g & 1) << 3);
                int acol = k0 + ((g >> 1) << 3);
                uint32_t off = (uint32_t)(arow * KCP + acol) * 2;
                ldsm_x4(ah, sAh_b + off);
                ldsm_x4(al, sAl_b + off);
            }
#pragma unroll
            for (int np = 0; np < N / 16; np++) {
                int nrow = np * 16 + r8 + ((g >> 1) << 3);
                int kcol = k0 + ((g & 1) << 3);
                uint32_t boff = (uint32_t)(nrow * KCP + kcol) * 2;
                uint32_t bh[4], bl[4];
                ldsm_x4(bh, sWh_b + boff);
                ldsm_x4(bl, sWl_b + boff);
                mma_bf16(acc[2 * np],     ah, bh);
                mma_bf16(acc[2 * np],     ah, bl);
                mma_bf16(acc[2 * np],     al, bh);
                mma_bf16(acc[2 * np + 1], ah, bh + 2);
                mma_bf16(acc[2 * np + 1], ah, bl + 2);
                mma_bf16(acc[2 * np + 1], al, bh + 2);
            }
        }
    }

    // --- epilogue: scale by dinv[row], store ---
    int r0 = rowBase + wrow + (lane >> 2);
    int r1 = r0 + 8;
    int cbase = (lane & 3) * 2;
    float s0 = (r0 < NN) ? g_dinv[r0] : 0.f;
    float s1 = (r1 < NN) ? g_dinv[r1] : 0.f;
#pragma unroll
    for (int t = 0; t < N / 8; t++) {
        int col = t * 8 + cbase;
        if (r0 < NN)
            *reinterpret_cast<float2*>(C + (size_t)r0 * N + col) =
                make_float2(acc[t][0] * s0, acc[t][1] * s0);
        if (r1 < NN)
            *reinterpret_cast<float2*>(C + (size_t)r1 * N + col) =
                make_float2(acc[t][2] * s1, acc[t][3] * s1);
    }
}

__global__ void __launch_bounds__(256)
k_gemm1(const float* __restrict__ x) {
    mma_gemm_core<IN_C, HID_C>(x, g_Wt1h, g_Wt1l, g_h1);
}
__global__ void __launch_bounds__(256)
k_gemm2() {
    mma_gemm_core<HID_C, OUT_C>(g_t1, g_Wt2h, g_Wt2l, g_h2);
}

// ---------------------------------------------------------------------------
// Aggregation: out[i] = act( dinv[i] * (hs[i] + sum_{s in N(i)} hs[s]) + b )
// ---------------------------------------------------------------------------
template <int C, bool RELU>
__device__ __forceinline__ void aggregate_core(
        const float* __restrict__ hs, const float* __restrict__ bias,
        float* __restrict__ out) {
    constexpr int G   = C / 4;
    constexpr int NPB = 128 / G;
    const int local = threadIdx.x / G;
    const int lane  = threadIdx.x % G;
    const int node  = blockIdx.x * NPB + local;
    if (node >= NN) return;

    const float4* base = reinterpret_cast<const float4*>(hs);
    float4 acc = base[(size_t)node * G + lane];
    const int beg = g_rowptr[node];
    const int end = g_rowptr[node + 1];
#pragma unroll 4
    for (int e = beg; e < end; e++) {
        int s = g_csr[e];
        float4 v = base[(size_t)s * G + lane];
        acc.x += v.x; acc.y += v.y; acc.z += v.z; acc.w += v.w;
    }
    const float d = g_dinv[node];
    float4 b = reinterpret_cast<const float4*>(bias)[lane];
    acc.x = acc.x * d + b.x;
    acc.y = acc.y * d + b.y;
    acc.z = acc.z * d + b.z;
    acc.w = acc.w * d + b.w;
    if (RELU) {
        acc.x = fmaxf(acc.x, 0.f);
        acc.y = fmaxf(acc.y, 0.f);
        acc.z = fmaxf(acc.z, 0.f);
        acc.w = fmaxf(acc.w, 0.f);
    }
    reinterpret_cast<float4*>(out)[(size_t)node * G + lane] = acc;
}

__global__ void __launch_bounds__(128)
k_agg1(const float* __restrict__ b1) {
    aggregate_core<HID_C, true>(g_h1, b1, g_t1);
}
__global__ void __launch_bounds__(128)
k_agg2(const float* __restrict__ b2, float* __restrict__ out) {
    aggregate_core<OUT_C, false>(g_h2, b2, out);
}

// ---------------------------------------------------------------------------
// Launch
// ---------------------------------------------------------------------------
extern "C" void kernel_launch(void* const* d_in, const int* in_sizes, int n_in,
                              void* d_out, int out_size) {
    const float* x   = (const float*)d_in[0];
    const int*   ei  = (const int*)d_in[1];     // int32 edge_index
    const float* W1  = (const float*)d_in[2];
    const float* b1  = (const float*)d_in[3];
    const float* W2  = (const float*)d_in[4];
    const float* b2  = (const float*)d_in[5];
    float*       out = (float*)d_out;

    const int* src = ei;
    const int* dst = ei + EE;

    const int TB = 256;
    const int nBlkN = (NN + TB - 1) / TB;
    const int nBlkE = (EE + TB - 1) / TB;
    const int nScan = (NN + 1023) / 1024;

    // --- normalization + CSR build ---
    k_clear_deg<<<nBlkN, TB>>>();
    k_count_deg<<<nBlkE, TB>>>(dst);
    k_dinv<<<nBlkN, TB>>>();
    k_scan_block<<<nScan, 1024>>>();
    k_scan_sums<<<1, 32>>>(nScan);
    k_scan_add<<<nBlkN, TB>>>();
    k_fill_csr<<<nBlkE, TB>>>(src, dst);

    // --- weight images ---
    k_conv1<<<(IN_C * HID_C + 255) / 256, 256>>>(W1);
    k_conv2<<<(HID_C * OUT_C + 255) / 256, 256>>>(W2);

    const int nTiles = (NN + 127) / 128;   // 391

    // --- layer 1 ---
    k_gemm1<<<nTiles, 256>>>(x);
    {
        constexpr int NPB = 128 / (HID_C / 4);
        int grid = (NN + NPB - 1) / NPB;
        k_agg1<<<grid, 128>>>(b1);
    }
    // --- layer 2 ---
    k_gemm2<<<nTiles, 256>>>();
    {
        constexpr int NPB = 128 / (OUT_C / 4);
        int grid = (NN + NPB - 1) / NPB;
        k_agg2<<<grid, 128>>>(b2, out);
    }
}

// round 12
// speedup vs baseline: 3.0927x; 1.2741x over previous
#include <cuda_runtime.h>
#include <cuda_bf16.h>
#include <cstdint>

// Problem constants (fixed by the dataset)
#define NN 50000
#define EE 800000
#define IN_C 256
#define HID_C 128
#define OUT_C 64

// ---------------------------------------------------------------------------
// Scratch (device globals). All float4-accessed buffers 16B-aligned.
// ---------------------------------------------------------------------------
__device__ int   g_deg[NN];
__device__ float g_dinv[NN];
__device__ int   g_rowptr[NN + 1];
__device__ int   g_cursor[NN];
__device__ int   g_blocksums[64];
__device__ int   g_csr[EE];
__device__ __align__(16) float g_h1[(size_t)NN * HID_C];
__device__ __align__(16) float g_t1[(size_t)NN * HID_C];
__device__ __align__(16) float g_h2[(size_t)NN * OUT_C];
// Weight images: W^T in bf16 hi/lo, row-major [n][k] (k contiguous)
__device__ __align__(16) __nv_bfloat16 g_Wt1h[HID_C * IN_C];
__device__ __align__(16) __nv_bfloat16 g_Wt1l[HID_C * IN_C];
__device__ __align__(16) __nv_bfloat16 g_Wt2h[OUT_C * HID_C];
__device__ __align__(16) __nv_bfloat16 g_Wt2l[OUT_C * HID_C];

// ---------------------------------------------------------------------------
// PTX helpers (arch-agnostic: ldmatrix sm_75+, mma bf16 sm_80+)
// ---------------------------------------------------------------------------
__device__ __forceinline__ uint32_t smem_u32(const void* p) {
    uint32_t a;
    asm("{ .reg .u64 t; cvta.to.shared.u64 t, %1; cvt.u32.u64 %0, t; }"
        : "=r"(a) : "l"(p));
    return a;
}
__device__ __forceinline__ void ldsm_x4(uint32_t* r, uint32_t addr) {
    asm volatile("ldmatrix.sync.aligned.m8n8.x4.shared.b16 {%0,%1,%2,%3}, [%4];"
                 : "=r"(r[0]), "=r"(r[1]), "=r"(r[2]), "=r"(r[3]) : "r"(addr));
}
__device__ __forceinline__ void mma_bf16(float* d, const uint32_t* a,
                                         const uint32_t* b) {
    asm volatile(
        "mma.sync.aligned.m16n8k16.row.col.f32.bf16.bf16.f32 "
        "{%0,%1,%2,%3}, {%4,%5,%6,%7}, {%8,%9}, {%0,%1,%2,%3};"
        : "+f"(d[0]), "+f"(d[1]), "+f"(d[2]), "+f"(d[3])
        : "r"(a[0]), "r"(a[1]), "r"(a[2]), "r"(a[3]), "r"(b[0]), "r"(b[1]));
}
__device__ __forceinline__ uint32_t pack2(__nv_bfloat16 lo, __nv_bfloat16 hi) {
    return ((uint32_t)__bfloat16_as_ushort(hi) << 16) | __bfloat16_as_ushort(lo);
}

// ---------------------------------------------------------------------------
// Degree / norm. edge_index is INT32 (JAX x64 disabled).
// ---------------------------------------------------------------------------
__global__ void k_clear_deg() {
    int i = blockIdx.x * blockDim.x + threadIdx.x;
    if (i < NN) g_deg[i] = 0;
}
__global__ void k_count_deg(const int* __restrict__ dst) {
    int e = blockIdx.x * blockDim.x + threadIdx.x;
    if (e < EE) {
        unsigned d = (unsigned)dst[e];
        if (d < NN) atomicAdd(&g_deg[d], 1);
    }
}
__global__ void k_scan_block() {
    __shared__ int sm[1024];
    int i = blockIdx.x * 1024 + threadIdx.x;
    int v = (i < NN) ? g_deg[i] : 0;
    sm[threadIdx.x] = v;
    __syncthreads();
#pragma unroll
    for (int off = 1; off < 1024; off <<= 1) {
        int t = (threadIdx.x >= off) ? sm[threadIdx.x - off] : 0;
        __syncthreads();
        sm[threadIdx.x] += t;
        __syncthreads();
    }
    int incl = sm[threadIdx.x];
    if (i < NN) g_rowptr[i] = incl - v;
    if (threadIdx.x == 1023) g_blocksums[blockIdx.x] = incl;
}
// Merged: cross-block scan offset + rowptr/cursor finalize + dinv.
__global__ void k_scan_add() {
    int i = blockIdx.x * blockDim.x + threadIdx.x;
    if (i < NN) {
        int blk = i >> 10;
        int off = 0;
        for (int b = 0; b < blk; b++) off += g_blocksums[b];  // broadcast loads
        int r = g_rowptr[i] + off;
        g_rowptr[i] = r;
        g_cursor[i] = r;
        g_dinv[i] = rsqrtf((float)(g_deg[i] + 1));
    }
    if (i == 0) g_rowptr[NN] = EE;
}
__global__ void k_fill_csr(const int* __restrict__ src,
                           const int* __restrict__ dst) {
    int e = blockIdx.x * blockDim.x + threadIdx.x;
    if (e < EE) {
        unsigned d = (unsigned)dst[e];
        unsigned s = (unsigned)src[e];
        if (d < NN && s < NN) {
            int pos = atomicAdd(&g_cursor[d], 1);
            if ((unsigned)pos < EE) g_csr[pos] = (int)s;
        }
    }
}

// ---------------------------------------------------------------------------
// Weight split (merged W1+W2): W[K,N] fp32 -> hi/lo bf16, layout [n][k]
// ---------------------------------------------------------------------------
__global__ void k_conv(const float* __restrict__ W1, const float* __restrict__ W2) {
    int i = blockIdx.x * blockDim.x + threadIdx.x;
    constexpr int T1 = IN_C * HID_C;
    constexpr int T2 = HID_C * OUT_C;
    if (i < T1) {
        int k = i / HID_C, n = i % HID_C;
        float v = W1[i];
        __nv_bfloat16 h = __float2bfloat16(v);
        __nv_bfloat16 l = __float2bfloat16(v - __bfloat162float(h));
        g_Wt1h[(size_t)n * IN_C + k] = h;
        g_Wt1l[(size_t)n * IN_C + k] = l;
    } else if (i < T1 + T2) {
        int j = i - T1;
        int k = j / OUT_C, n = j % OUT_C;
        float v = W2[j];
        __nv_bfloat16 h = __float2bfloat16(v);
        __nv_bfloat16 l = __float2bfloat16(v - __bfloat162float(h));
        g_Wt2h[(size_t)n * HID_C + k] = h;
        g_Wt2l[(size_t)n * HID_C + k] = l;
    }
}

// ---------------------------------------------------------------------------
// bf16x3 HMMA GEMM with register-prefetch pipeline:
//   C[row,:] = (A[row,:] @ W) * g_dinv[row]
//   CTA: 128 rows x N, 8 warps. K-chunks of 32; chunk c+1's global loads are
//   issued before chunk c's MMAs so LDG latency hides under tensor work.
// ---------------------------------------------------------------------------
template <int K, int N>
__device__ __forceinline__ void mma_gemm_core(
        const float* __restrict__ A,
        const __nv_bfloat16* __restrict__ Wth,
        const __nv_bfloat16* __restrict__ Wtl,
        float* __restrict__ C) {
    constexpr int KC  = 32;   // k per chunk
    constexpr int KCP = 40;   // row stride in bf16 (80B: 16B-mult, conflict-free)
    constexpr int KCH = K / KC;
    constexpr int WU  = N / 64;   // W prefetch regs per image (uint4)
    __shared__ __align__(16) __nv_bfloat16 sAh[128 * KCP];
    __shared__ __align__(16) __nv_bfloat16 sAl[128 * KCP];
    __shared__ __align__(16) __nv_bfloat16 sWh[N * KCP];
    __shared__ __align__(16) __nv_bfloat16 sWl[N * KCP];

    const int tid  = threadIdx.x;
    const int lane = tid & 31;
    const int warp = tid >> 5;
    const int wrow = warp * 16;
    const int rowBase = blockIdx.x * 128;

    const uint32_t sAh_b = smem_u32(sAh), sAl_b = smem_u32(sAl);
    const uint32_t sWh_b = smem_u32(sWh), sWl_b = smem_u32(sWl);

    float acc[N / 8][4];
#pragma unroll
    for (int t = 0; t < N / 8; t++)
#pragma unroll
        for (int q = 0; q < 4; q++) acc[t][q] = 0.f;

    const int g  = lane >> 3;       // ldmatrix lane-group
    const int r8 = lane & 7;

    // prefetch registers
    float4 pa[4];
    uint4  pwh[WU], pwl[WU];

    auto loadA = [&](int c) {
#pragma unroll
        for (int u = 0; u < 4; u++) {
            int i = tid + u * 256;
            int r = i >> 3, kq = i & 7;
            int grow = rowBase + r;
            pa[u] = make_float4(0.f, 0.f, 0.f, 0.f);
            if (grow < NN)
                pa[u] = *reinterpret_cast<const float4*>(
                            A + (size_t)grow * K + c * KC + kq * 4);
        }
    };
    auto loadW = [&](int c) {
#pragma unroll
        for (int u = 0; u < WU; u++) {
            int i = tid + u * 256;        // i in [0, N*4)
            int n = i >> 2, q = i & 3;
            pwh[u] = *reinterpret_cast<const uint4*>(
                         Wth + (size_t)n * K + c * KC + q * 8);
            pwl[u] = *reinterpret_cast<const uint4*>(
                         Wtl + (size_t)n * K + c * KC + q * 8);
        }
    };
    auto storeAW = [&]() {
#pragma unroll
        for (int u = 0; u < 4; u++) {
            int i = tid + u * 256;
            int r = i >> 3, kq = i & 7;
            float4 v = pa[u];
            __nv_bfloat16 hx = __float2bfloat16(v.x), hy = __float2bfloat16(v.y);
            __nv_bfloat16 hz = __float2bfloat16(v.z), hw = __float2bfloat16(v.w);
            __nv_bfloat16 lx = __float2bfloat16(v.x - __bfloat162float(hx));
            __nv_bfloat16 ly = __float2bfloat16(v.y - __bfloat162float(hy));
            __nv_bfloat16 lz = __float2bfloat16(v.z - __bfloat162float(hz));
            __nv_bfloat16 lw = __float2bfloat16(v.w - __bfloat162float(hw));
            *reinterpret_cast<uint2*>(&sAh[r * KCP + kq * 4]) =
                make_uint2(pack2(hx, hy), pack2(hz, hw));
            *reinterpret_cast<uint2*>(&sAl[r * KCP + kq * 4]) =
                make_uint2(pack2(lx, ly), pack2(lz, lw));
        }
#pragma unroll
        for (int u = 0; u < WU; u++) {
            int i = tid + u * 256;
            int n = i >> 2, q = i & 3;
            *reinterpret_cast<uint4*>(&sWh[n * KCP + q * 8]) = pwh[u];
            *reinterpret_cast<uint4*>(&sWl[n * KCP + q * 8]) = pwl[u];
        }
    };

    loadA(0);
    loadW(0);

    for (int c = 0; c < KCH; c++) {
        if (c) __syncthreads();      // prior chunk's MMAs done before overwrite
        storeAW();
        __syncthreads();
        if (c + 1 < KCH) {           // issue next chunk's LDGs before MMAs
            loadA(c + 1);
            loadW(c + 1);
        }

#pragma unroll
        for (int ks = 0; ks < KC / 16; ks++) {
            int k0 = ks * 16;
            uint32_t ah[4], al[4];
            {
                int arow = wrow + r8 + ((g & 1) << 3);
                int acol = k0 + ((g >> 1) << 3);
                uint32_t off = (uint32_t)(arow * KCP + acol) * 2;
                ldsm_x4(ah, sAh_b + off);
                ldsm_x4(al, sAl_b + off);
            }
#pragma unroll
            for (int np = 0; np < N / 16; np++) {
                int nrow = np * 16 + r8 + ((g >> 1) << 3);
                int kcol = k0 + ((g & 1) << 3);
                uint32_t boff = (uint32_t)(nrow * KCP + kcol) * 2;
                uint32_t bh[4], bl[4];
                ldsm_x4(bh, sWh_b + boff);
                ldsm_x4(bl, sWl_b + boff);
                mma_bf16(acc[2 * np],     ah, bh);
                mma_bf16(acc[2 * np],     ah, bl);
                mma_bf16(acc[2 * np],     al, bh);
                mma_bf16(acc[2 * np + 1], ah, bh + 2);
                mma_bf16(acc[2 * np + 1], ah, bl + 2);
                mma_bf16(acc[2 * np + 1], al, bh + 2);
            }
        }
    }

    // --- epilogue: scale by dinv[row], store ---
    int r0 = rowBase + wrow + (lane >> 2);
    int r1 = r0 + 8;
    int cbase = (lane & 3) * 2;
    float s0 = (r0 < NN) ? g_dinv[r0] : 0.f;
    float s1 = (r1 < NN) ? g_dinv[r1] : 0.f;
#pragma unroll
    for (int t = 0; t < N / 8; t++) {
        int col = t * 8 + cbase;
        if (r0 < NN)
            *reinterpret_cast<float2*>(C + (size_t)r0 * N + col) =
                make_float2(acc[t][0] * s0, acc[t][1] * s0);
        if (r1 < NN)
            *reinterpret_cast<float2*>(C + (size_t)r1 * N + col) =
                make_float2(acc[t][2] * s1, acc[t][3] * s1);
    }
}

__global__ void __launch_bounds__(256)
k_gemm1(const float* __restrict__ x) {
    mma_gemm_core<IN_C, HID_C>(x, g_Wt1h, g_Wt1l, g_h1);
}
__global__ void __launch_bounds__(256)
k_gemm2() {
    mma_gemm_core<HID_C, OUT_C>(g_t1, g_Wt2h, g_Wt2l, g_h2);
}

// ---------------------------------------------------------------------------
// Aggregation: out[i] = act( dinv[i] * (hs[i] + sum_{s in N(i)} hs[s]) + b )
// ---------------------------------------------------------------------------
template <int C, bool RELU>
__device__ __forceinline__ void aggregate_core(
        const float* __restrict__ hs, const float* __restrict__ bias,
        float* __restrict__ out) {
    constexpr int G   = C / 4;
    constexpr int NPB = 128 / G;
    const int local = threadIdx.x / G;
    const int lane  = threadIdx.x % G;
    const int node  = blockIdx.x * NPB + local;
    if (node >= NN) return;

    const float4* base = reinterpret_cast<const float4*>(hs);
    float4 acc = base[(size_t)node * G + lane];
    const int beg = g_rowptr[node];
    const int end = g_rowptr[node + 1];
#pragma unroll 4
    for (int e = beg; e < end; e++) {
        int s = g_csr[e];
        float4 v = base[(size_t)s * G + lane];
        acc.x += v.x; acc.y += v.y; acc.z += v.z; acc.w += v.w;
    }
    const float d = g_dinv[node];
    float4 b = reinterpret_cast<const float4*>(bias)[lane];
    acc.x = acc.x * d + b.x;
    acc.y = acc.y * d + b.y;
    acc.z = acc.z * d + b.z;
    acc.w = acc.w * d + b.w;
    if (RELU) {
        acc.x = fmaxf(acc.x, 0.f);
        acc.y = fmaxf(acc.y, 0.f);
        acc.z = fmaxf(acc.z, 0.f);
        acc.w = fmaxf(acc.w, 0.f);
    }
    reinterpret_cast<float4*>(out)[(size_t)node * G + lane] = acc;
}

__global__ void __launch_bounds__(128)
k_agg1(const float* __restrict__ b1) {
    aggregate_core<HID_C, true>(g_h1, b1, g_t1);
}
__global__ void __launch_bounds__(128)
k_agg2(const float* __restrict__ b2, float* __restrict__ out) {
    aggregate_core<OUT_C, false>(g_h2, b2, out);
}

// ---------------------------------------------------------------------------
// Launch (10 kernels)
// ---------------------------------------------------------------------------
extern "C" void kernel_launch(void* const* d_in, const int* in_sizes, int n_in,
                              void* d_out, int out_size) {
    const float* x   = (const float*)d_in[0];
    const int*   ei  = (const int*)d_in[1];     // int32 edge_index
    const float* W1  = (const float*)d_in[2];
    const float* b1  = (const float*)d_in[3];
    const float* W2  = (const float*)d_in[4];
    const float* b2  = (const float*)d_in[5];
    float*       out = (float*)d_out;

    const int* src = ei;
    const int* dst = ei + EE;

    const int TB = 256;
    const int nBlkN = (NN + TB - 1) / TB;
    const int nBlkE = (EE + TB - 1) / TB;
    const int nScan = (NN + 1023) / 1024;

    // --- normalization + CSR build ---
    k_clear_deg<<<nBlkN, TB>>>();
    k_count_deg<<<nBlkE, TB>>>(dst);
    k_scan_block<<<nScan, 1024>>>();
    k_scan_add<<<nBlkN, TB>>>();          // + dinv + cursor (merged)
    k_fill_csr<<<nBlkE, TB>>>(src, dst);

    // --- weight images (merged) ---
    {
        constexpr int TOT = IN_C * HID_C + HID_C * OUT_C;
        k_conv<<<(TOT + 255) / 256, 256>>>(W1, W2);
    }

    const int nTiles = (NN + 127) / 128;   // 391

    // --- layer 1 ---
    k_gemm1<<<nTiles, 256>>>(x);
    {
        constexpr int NPB = 128 / (HID_C / 4);
        int grid = (NN + NPB - 1) / NPB;
        k_agg1<<<grid, 128>>>(b1);
    }
    // --- layer 2 ---
    k_gemm2<<<nTiles, 256>>>();
    {
        constexpr int NPB = 128 / (OUT_C / 4);
        int grid = (NN + NPB - 1) / NPB;
        k_agg2<<<grid, 128>>>(b2, out);
    }
}

// round 13
// speedup vs baseline: 3.3157x; 1.0721x over previous
#include <cuda_runtime.h>
#include <cuda_bf16.h>
#include <cstdint>

// Problem constants (fixed by the dataset)
#define NN 50000
#define EE 800000
#define IN_C 256
#define HID_C 128
#define OUT_C 64

// ---------------------------------------------------------------------------
// Scratch (device globals). All float4-accessed buffers 16B-aligned.
// ---------------------------------------------------------------------------
__device__ int   g_deg[NN];
__device__ float g_dinv[NN];
__device__ int   g_rowptr[NN + 1];
__device__ int   g_cursor[NN];
__device__ int   g_blocksums[64];
__device__ int   g_csr[EE];
__device__ __align__(16) float g_h1[(size_t)NN * HID_C];
__device__ __align__(16) float g_t1[(size_t)NN * HID_C];
__device__ __align__(16) float g_h2[(size_t)NN * OUT_C];
// Weight images: W^T in bf16 hi/lo, row-major [n][k] (k contiguous)
__device__ __align__(16) __nv_bfloat16 g_Wt1h[HID_C * IN_C];
__device__ __align__(16) __nv_bfloat16 g_Wt1l[HID_C * IN_C];
__device__ __align__(16) __nv_bfloat16 g_Wt2h[OUT_C * HID_C];
__device__ __align__(16) __nv_bfloat16 g_Wt2l[OUT_C * HID_C];

// ---------------------------------------------------------------------------
// Side stream + events for fork-join overlap (created once at process init;
// no device memory involved, no per-call static guards).
// ---------------------------------------------------------------------------
struct StreamBundle {
    cudaStream_t s1;
    cudaEvent_t  ev_start, ev_deg, ev_gemm1;
    StreamBundle() {
        cudaStreamCreateWithFlags(&s1, cudaStreamNonBlocking);
        cudaEventCreateWithFlags(&ev_start, cudaEventDisableTiming);
        cudaEventCreateWithFlags(&ev_deg,   cudaEventDisableTiming);
        cudaEventCreateWithFlags(&ev_gemm1, cudaEventDisableTiming);
    }
};
static StreamBundle g_sb;

// ---------------------------------------------------------------------------
// PTX helpers (arch-agnostic: ldmatrix sm_75+, mma bf16 sm_80+)
// ---------------------------------------------------------------------------
__device__ __forceinline__ uint32_t smem_u32(const void* p) {
    uint32_t a;
    asm("{ .reg .u64 t; cvta.to.shared.u64 t, %1; cvt.u32.u64 %0, t; }"
        : "=r"(a) : "l"(p));
    return a;
}
__device__ __forceinline__ void ldsm_x4(uint32_t* r, uint32_t addr) {
    asm volatile("ldmatrix.sync.aligned.m8n8.x4.shared.b16 {%0,%1,%2,%3}, [%4];"
                 : "=r"(r[0]), "=r"(r[1]), "=r"(r[2]), "=r"(r[3]) : "r"(addr));
}
__device__ __forceinline__ void mma_bf16(float* d, const uint32_t* a,
                                         const uint32_t* b) {
    asm volatile(
        "mma.sync.aligned.m16n8k16.row.col.f32.bf16.bf16.f32 "
        "{%0,%1,%2,%3}, {%4,%5,%6,%7}, {%8,%9}, {%0,%1,%2,%3};"
        : "+f"(d[0]), "+f"(d[1]), "+f"(d[2]), "+f"(d[3])
        : "r"(a[0]), "r"(a[1]), "r"(a[2]), "r"(a[3]), "r"(b[0]), "r"(b[1]));
}
__device__ __forceinline__ uint32_t pack2(__nv_bfloat16 lo, __nv_bfloat16 hi) {
    return ((uint32_t)__bfloat16_as_ushort(hi) << 16) | __bfloat16_as_ushort(lo);
}

// ---------------------------------------------------------------------------
// Degree / norm. edge_index is INT32 (JAX x64 disabled).
// ---------------------------------------------------------------------------
__global__ void k_clear_deg() {
    int i = blockIdx.x * blockDim.x + threadIdx.x;
    if (i < NN) g_deg[i] = 0;
}
__global__ void k_count_deg(const int* __restrict__ dst) {
    int e = blockIdx.x * blockDim.x + threadIdx.x;
    if (e < EE) {
        unsigned d = (unsigned)dst[e];
        if (d < NN) atomicAdd(&g_deg[d], 1);
    }
}
__global__ void k_dinv() {
    int i = blockIdx.x * blockDim.x + threadIdx.x;
    if (i < NN) g_dinv[i] = rsqrtf((float)(g_deg[i] + 1));  // +1 self-loop
}
__global__ void k_scan_block() {
    __shared__ int sm[1024];
    int i = blockIdx.x * 1024 + threadIdx.x;
    int v = (i < NN) ? g_deg[i] : 0;
    sm[threadIdx.x] = v;
    __syncthreads();
#pragma unroll
    for (int off = 1; off < 1024; off <<= 1) {
        int t = (threadIdx.x >= off) ? sm[threadIdx.x - off] : 0;
        __syncthreads();
        sm[threadIdx.x] += t;
        __syncthreads();
    }
    int incl = sm[threadIdx.x];
    if (i < NN) g_rowptr[i] = incl - v;
    if (threadIdx.x == 1023) g_blocksums[blockIdx.x] = incl;
}
// Cross-block scan offset + rowptr/cursor finalize.
__global__ void k_scan_add() {
    int i = blockIdx.x * blockDim.x + threadIdx.x;
    if (i < NN) {
        int blk = i >> 10;
        int off = 0;
        for (int b = 0; b < blk; b++) off += g_blocksums[b];  // broadcast loads
        int r = g_rowptr[i] + off;
        g_rowptr[i] = r;
        g_cursor[i] = r;
    }
    if (i == 0) g_rowptr[NN] = EE;
}
__global__ void k_fill_csr(const int* __restrict__ src,
                           const int* __restrict__ dst) {
    int e = blockIdx.x * blockDim.x + threadIdx.x;
    if (e < EE) {
        unsigned d = (unsigned)dst[e];
        unsigned s = (unsigned)src[e];
        if (d < NN && s < NN) {
            int pos = atomicAdd(&g_cursor[d], 1);
            if ((unsigned)pos < EE) g_csr[pos] = (int)s;
        }
    }
}

// ---------------------------------------------------------------------------
// Weight split (merged W1+W2): W[K,N] fp32 -> hi/lo bf16, layout [n][k]
// ---------------------------------------------------------------------------
__global__ void k_conv(const float* __restrict__ W1, const float* __restrict__ W2) {
    int i = blockIdx.x * blockDim.x + threadIdx.x;
    constexpr int T1 = IN_C * HID_C;
    constexpr int T2 = HID_C * OUT_C;
    if (i < T1) {
        int k = i / HID_C, n = i % HID_C;
        float v = W1[i];
        __nv_bfloat16 h = __float2bfloat16(v);
        __nv_bfloat16 l = __float2bfloat16(v - __bfloat162float(h));
        g_Wt1h[(size_t)n * IN_C + k] = h;
        g_Wt1l[(size_t)n * IN_C + k] = l;
    } else if (i < T1 + T2) {
        int j = i - T1;
        int k = j / OUT_C, n = j % OUT_C;
        float v = W2[j];
        __nv_bfloat16 h = __float2bfloat16(v);
        __nv_bfloat16 l = __float2bfloat16(v - __bfloat162float(h));
        g_Wt2h[(size_t)n * HID_C + k] = h;
        g_Wt2l[(size_t)n * HID_C + k] = l;
    }
}

// ---------------------------------------------------------------------------
// bf16x3 HMMA GEMM with register-prefetch pipeline:
//   C[row,:] = (A[row,:] @ W) * g_dinv[row]
// ---------------------------------------------------------------------------
template <int K, int N>
__device__ __forceinline__ void mma_gemm_core(
        const float* __restrict__ A,
        const __nv_bfloat16* __restrict__ Wth,
        const __nv_bfloat16* __restrict__ Wtl,
        float* __restrict__ C) {
    constexpr int KC  = 32;   // k per chunk
    constexpr int KCP = 40;   // row stride in bf16 (80B: 16B-mult, conflict-free)
    constexpr int KCH = K / KC;
    constexpr int WU  = N / 64;   // W prefetch regs per image (uint4)
    __shared__ __align__(16) __nv_bfloat16 sAh[128 * KCP];
    __shared__ __align__(16) __nv_bfloat16 sAl[128 * KCP];
    __shared__ __align__(16) __nv_bfloat16 sWh[N * KCP];
    __shared__ __align__(16) __nv_bfloat16 sWl[N * KCP];

    const int tid  = threadIdx.x;
    const int lane = tid & 31;
    const int warp = tid >> 5;
    const int wrow = warp * 16;
    const int rowBase = blockIdx.x * 128;

    const uint32_t sAh_b = smem_u32(sAh), sAl_b = smem_u32(sAl);
    const uint32_t sWh_b = smem_u32(sWh), sWl_b = smem_u32(sWl);

    float acc[N / 8][4];
#pragma unroll
    for (int t = 0; t < N / 8; t++)
#pragma unroll
        for (int q = 0; q < 4; q++) acc[t][q] = 0.f;

    const int g  = lane >> 3;       // ldmatrix lane-group
    const int r8 = lane & 7;

    // prefetch registers
    float4 pa[4];
    uint4  pwh[WU], pwl[WU];

    auto loadA = [&](int c) {
#pragma unroll
        for (int u = 0; u < 4; u++) {
            int i = tid + u * 256;
            int r = i >> 3, kq = i & 7;
            int grow = rowBase + r;
            pa[u] = make_float4(0.f, 0.f, 0.f, 0.f);
            if (grow < NN)
                pa[u] = *reinterpret_cast<const float4*>(
                            A + (size_t)grow * K + c * KC + kq * 4);
        }
    };
    auto loadW = [&](int c) {
#pragma unroll
        for (int u = 0; u < WU; u++) {
            int i = tid + u * 256;        // i in [0, N*4)
            int n = i >> 2, q = i & 3;
            pwh[u] = *reinterpret_cast<const uint4*>(
                         Wth + (size_t)n * K + c * KC + q * 8);
            pwl[u] = *reinterpret_cast<const uint4*>(
                         Wtl + (size_t)n * K + c * KC + q * 8);
        }
    };
    auto storeAW = [&]() {
#pragma unroll
        for (int u = 0; u < 4; u++) {
            int i = tid + u * 256;
            int r = i >> 3, kq = i & 7;
            float4 v = pa[u];
            __nv_bfloat16 hx = __float2bfloat16(v.x), hy = __float2bfloat16(v.y);
            __nv_bfloat16 hz = __float2bfloat16(v.z), hw = __float2bfloat16(v.w);
            __nv_bfloat16 lx = __float2bfloat16(v.x - __bfloat162float(hx));
            __nv_bfloat16 ly = __float2bfloat16(v.y - __bfloat162float(hy));
            __nv_bfloat16 lz = __float2bfloat16(v.z - __bfloat162float(hz));
            __nv_bfloat16 lw = __float2bfloat16(v.w - __bfloat162float(hw));
            *reinterpret_cast<uint2*>(&sAh[r * KCP + kq * 4]) =
                make_uint2(pack2(hx, hy), pack2(hz, hw));
            *reinterpret_cast<uint2*>(&sAl[r * KCP + kq * 4]) =
                make_uint2(pack2(lx, ly), pack2(lz, lw));
        }
#pragma unroll
        for (int u = 0; u < WU; u++) {
            int i = tid + u * 256;
            int n = i >> 2, q = i & 3;
            *reinterpret_cast<uint4*>(&sWh[n * KCP + q * 8]) = pwh[u];
            *reinterpret_cast<uint4*>(&sWl[n * KCP + q * 8]) = pwl[u];
        }
    };

    loadA(0);
    loadW(0);

    for (int c = 0; c < KCH; c++) {
        if (c) __syncthreads();      // prior chunk's MMAs done before overwrite
        storeAW();
        __syncthreads();
        if (c + 1 < KCH) {           // issue next chunk's LDGs before MMAs
            loadA(c + 1);
            loadW(c + 1);
        }

#pragma unroll
        for (int ks = 0; ks < KC / 16; ks++) {
            int k0 = ks * 16;
            uint32_t ah[4], al[4];
            {
                int arow = wrow + r8 + ((g & 1) << 3);
                int acol = k0 + ((g >> 1) << 3);
                uint32_t off = (uint32_t)(arow * KCP + acol) * 2;
                ldsm_x4(ah, sAh_b + off);
                ldsm_x4(al, sAl_b + off);
            }
#pragma unroll
            for (int np = 0; np < N / 16; np++) {
                int nrow = np * 16 + r8 + ((g >> 1) << 3);
                int kcol = k0 + ((g & 1) << 3);
                uint32_t boff = (uint32_t)(nrow * KCP + kcol) * 2;
                uint32_t bh[4], bl[4];
                ldsm_x4(bh, sWh_b + boff);
                ldsm_x4(bl, sWl_b + boff);
                mma_bf16(acc[2 * np],     ah, bh);
                mma_bf16(acc[2 * np],     ah, bl);
                mma_bf16(acc[2 * np],     al, bh);
                mma_bf16(acc[2 * np + 1], ah, bh + 2);
                mma_bf16(acc[2 * np + 1], ah, bl + 2);
                mma_bf16(acc[2 * np + 1], al, bh + 2);
            }
        }
    }

    // --- epilogue: scale by dinv[row], store ---
    int r0 = rowBase + wrow + (lane >> 2);
    int r1 = r0 + 8;
    int cbase = (lane & 3) * 2;
    float s0 = (r0 < NN) ? g_dinv[r0] : 0.f;
    float s1 = (r1 < NN) ? g_dinv[r1] : 0.f;
#pragma unroll
    for (int t = 0; t < N / 8; t++) {
        int col = t * 8 + cbase;
        if (r0 < NN)
            *reinterpret_cast<float2*>(C + (size_t)r0 * N + col) =
                make_float2(acc[t][0] * s0, acc[t][1] * s0);
        if (r1 < NN)
            *reinterpret_cast<float2*>(C + (size_t)r1 * N + col) =
                make_float2(acc[t][2] * s1, acc[t][3] * s1);
    }
}

__global__ void __launch_bounds__(256)
k_gemm1(const float* __restrict__ x) {
    mma_gemm_core<IN_C, HID_C>(x, g_Wt1h, g_Wt1l, g_h1);
}
__global__ void __launch_bounds__(256)
k_gemm2() {
    mma_gemm_core<HID_C, OUT_C>(g_t1, g_Wt2h, g_Wt2l, g_h2);
}

// ---------------------------------------------------------------------------
// Aggregation: out[i] = act( dinv[i] * (hs[i] + sum_{s in N(i)} hs[s]) + b )
// ---------------------------------------------------------------------------
template <int C, bool RELU>
__device__ __forceinline__ void aggregate_core(
        const float* __restrict__ hs, const float* __restrict__ bias,
        float* __restrict__ out) {
    constexpr int G   = C / 4;
    constexpr int NPB = 128 / G;
    const int local = threadIdx.x / G;
    const int lane  = threadIdx.x % G;
    const int node  = blockIdx.x * NPB + local;
    if (node >= NN) return;

    const float4* base = reinterpret_cast<const float4*>(hs);
    float4 acc = base[(size_t)node * G + lane];
    const int beg = g_rowptr[node];
    const int end = g_rowptr[node + 1];
#pragma unroll 4
    for (int e = beg; e < end; e++) {
        int s = g_csr[e];
        float4 v = base[(size_t)s * G + lane];
        acc.x += v.x; acc.y += v.y; acc.z += v.z; acc.w += v.w;
    }
    const float d = g_dinv[node];
    float4 b = reinterpret_cast<const float4*>(bias)[lane];
    acc.x = acc.x * d + b.x;
    acc.y = acc.y * d + b.y;
    acc.z = acc.z * d + b.z;
    acc.w = acc.w * d + b.w;
    if (RELU) {
        acc.x = fmaxf(acc.x, 0.f);
        acc.y = fmaxf(acc.y, 0.f);
        acc.z = fmaxf(acc.z, 0.f);
        acc.w = fmaxf(acc.w, 0.f);
    }
    reinterpret_cast<float4*>(out)[(size_t)node * G + lane] = acc;
}

__global__ void __launch_bounds__(128)
k_agg1(const float* __restrict__ b1) {
    aggregate_core<HID_C, true>(g_h1, b1, g_t1);
}
__global__ void __launch_bounds__(128)
k_agg2(const float* __restrict__ b2, float* __restrict__ out) {
    aggregate_core<OUT_C, false>(g_h2, b2, out);
}

// ---------------------------------------------------------------------------
// Launch: fork-join across two streams (capture-legal event fork).
//   s0: clear -> count -> [ev_deg] -> scan_block -> scan_add -> fill_csr
//       -> wait(ev_gemm1) -> agg1 -> gemm2 -> agg2
//   s1: wait(ev_start) -> conv -> wait(ev_deg) -> dinv -> gemm1 -> [ev_gemm1]
// ---------------------------------------------------------------------------
extern "C" void kernel_launch(void* const* d_in, const int* in_sizes, int n_in,
                              void* d_out, int out_size) {
    const float* x   = (const float*)d_in[0];
    const int*   ei  = (const int*)d_in[1];     // int32 edge_index
    const float* W1  = (const float*)d_in[2];
    const float* b1  = (const float*)d_in[3];
    const float* W2  = (const float*)d_in[4];
    const float* b2  = (const float*)d_in[5];
    float*       out = (float*)d_out;

    const int* src = ei;
    const int* dst = ei + EE;

    const int TB = 256;
    const int nBlkN = (NN + TB - 1) / TB;
    const int nBlkE = (EE + TB - 1) / TB;
    const int nScan = (NN + 1023) / 1024;
    const int nTiles = (NN + 127) / 128;   // 391

    cudaStream_t s0 = 0;            // harness-captured (legacy) stream
    cudaStream_t s1 = g_sb.s1;

    // fork s1 off the captured stream
    cudaEventRecord(g_sb.ev_start, s0);
    cudaStreamWaitEvent(s1, g_sb.ev_start, 0);

    // s1: weight images (no deps)
    {
        constexpr int TOT = IN_C * HID_C + HID_C * OUT_C;
        k_conv<<<(TOT + 255) / 256, 256, 0, s1>>>(W1, W2);
    }

    // s0: degree
    k_clear_deg<<<nBlkN, TB, 0, s0>>>();
    k_count_deg<<<nBlkE, TB, 0, s0>>>(dst);
    cudaEventRecord(g_sb.ev_deg, s0);

    // s0: scan + csr (needs deg only)
    k_scan_block<<<nScan, 1024, 0, s0>>>();
    k_scan_add<<<nBlkN, TB, 0, s0>>>();
    k_fill_csr<<<nBlkE, TB, 0, s0>>>(src, dst);

    // s1: dinv (needs deg) then gemm1 (needs x, W images, dinv)
    cudaStreamWaitEvent(s1, g_sb.ev_deg, 0);
    k_dinv<<<nBlkN, TB, 0, s1>>>();
    k_gemm1<<<nTiles, 256, 0, s1>>>(x);
    cudaEventRecord(g_sb.ev_gemm1, s1);

    // join: agg1 needs csr (s0) + h1 (s1)
    cudaStreamWaitEvent(s0, g_sb.ev_gemm1, 0);
    {
        constexpr int NPB = 128 / (HID_C / 4);
        int grid = (NN + NPB - 1) / NPB;
        k_agg1<<<grid, 128, 0, s0>>>(b1);
    }
    k_gemm2<<<nTiles, 256, 0, s0>>>();
    {
        constexpr int NPB = 128 / (OUT_C / 4);
        int grid = (NN + NPB - 1) / NPB;
        k_agg2<<<grid, 128, 0, s0>>>(b2, out);
    }
}